// round 12
// baseline (speedup 1.0000x reference)
#include <cuda_runtime.h>
#include <cuda_bf16.h>
#include <cstdint>

#define T_LEN   512
#define BATCH   2048
#define NB      16            // batches per CTA
#define HID     64
#define THREADS 512           // 16 warps: (w&7) = 32-row slice, (w>>3) = batch half
#define HSTRIDE 36            // u32 words per batch row of H (bank-verified)
#define GP      260           // floats per batch row of gbuf (bank-verified)

#define HALF_BAR(h)                                                           \
    asm volatile("bar.sync %0, %1;" :: "r"(1 + (h)), "r"(256) : "memory")

static __device__ __forceinline__ float tanh_mufu(float x) {
    float r; asm("tanh.approx.f32 %0, %1;" : "=f"(r) : "f"(x)); return r;
}
static __device__ __forceinline__ float sigm(float x) {
    return fmaf(tanh_mufu(0.5f * x), 0.5f, 0.5f);
}
static __device__ __forceinline__ uint32_t pk2(__nv_bfloat16 a, __nv_bfloat16 b) {
    return ((uint32_t)__bfloat16_as_ushort(b) << 16) | (uint32_t)__bfloat16_as_ushort(a);
}
// split (a,b) into packed hi and lo bf16x2 words (low half = first element)
static __device__ __forceinline__ void split2(float a, float b,
                                              uint32_t& hi, uint32_t& lo) {
    __nv_bfloat16 ah = __float2bfloat16(a), bh = __float2bfloat16(b);
    __nv_bfloat16 al = __float2bfloat16(a - __bfloat162float(ah));
    __nv_bfloat16 bl = __float2bfloat16(b - __bfloat162float(bh));
    hi = pk2(ah, bh); lo = pk2(al, bl);
}

// Ampere-class HMMA: m16n8k16, A row-major bf16, B col-major bf16, f32 accum
#define MMA_BF16(d, a, b0v, b1v)                                              \
    asm volatile("mma.sync.aligned.m16n8k16.row.col.f32.bf16.bf16.f32 "        \
        "{%0,%1,%2,%3}, {%4,%5,%6,%7}, {%8,%9}, {%0,%1,%2,%3};"                \
        : "+f"((d)[0]), "+f"((d)[1]), "+f"((d)[2]), "+f"((d)[3])               \
        : "r"((a)[0]), "r"((a)[1]), "r"((a)[2]), "r"((a)[3]),                  \
          "r"(b0v), "r"(b1v))

__global__ __launch_bounds__(THREADS, 1)
void lstm_kernel(const float* __restrict__ x,
                 const float* __restrict__ w_ih,
                 const float* __restrict__ w_hh,
                 const float* __restrict__ b_ih,
                 const float* __restrict__ b_hh,
                 const float* __restrict__ w_fc,
                 const float* __restrict__ b_fc,
                 float* __restrict__ out)
{
    __shared__ uint32_t Hhi[NB * HSTRIDE];   // bf16x2 words: [b][k/2]
    __shared__ uint32_t Hlo[NB * HSTRIDE];
    __shared__ float    gbuf[NB * GP];       // [b][gate row]
    __shared__ float    x_sh[2][NB][64];

    const int tid  = threadIdx.x;
    const int lane = tid & 31;
    const int wid  = tid >> 5;
    const int wrow = wid & 7;                 // row-slice warp id
    const int bh8  = wid >> 3;                // batch half (0: b 0-7, 1: b 8-15)
    const int qid  = lane >> 2;               // fragment groupID
    const int tig  = lane & 3;                // thread-in-group
    const int b0   = blockIdx.x * NB;

    // ---- build resident W_hh fragments (hi/lo split), K = 64 exactly ----
    uint32_t whi[2][4][4], wlo[2][4][4];
    #pragma unroll
    for (int mt = 0; mt < 2; ++mt) {
        #pragma unroll
        for (int kt = 0; kt < 4; ++kt) {
            const int r0 = 32 * wrow + 16 * mt + qid;
            const int k0 = 16 * kt + 2 * tig;
            #pragma unroll
            for (int rr = 0; rr < 4; ++rr) {          // a0..a3
                const int g = r0 + ((rr & 1) ? 8 : 0);
                const int k = k0 + ((rr & 2) ? 8 : 0);
                float v0 = w_hh[g * HID + k];
                float v1 = w_hh[g * HID + k + 1];
                split2(v0, v1, whi[mt][kt][rr], wlo[mt][kt][rr]);
            }
        }
    }

    // ---- update-phase scalars: x/bias contribution for this thread's rows ----
    // warp = batch wid; units u0 = lane, u1 = lane+32; gate rows u + 64*gt
    float wih_r[8], bias_r[8];
    #pragma unroll
    for (int j = 0; j < 8; ++j) {
        const int u = (j < 4) ? lane : lane + 32;
        const int r = (j & 3) * 64 + u;            // gt = j&3 (i,f,g,o)
        wih_r[j]  = w_ih[r];                       // I == 1
        bias_r[j] = b_ih[r] + b_hh[r];
    }
    const float wfc0 = w_fc[lane], wfc1 = w_fc[lane + 32];
    const float bfc  = b_fc[0];
    float c0 = 0.f, c1 = 0.f;
    float po_pend = 0.f;                       // deferred output partial

    // ---- init H = 0; stage x chunk 0 ----
    for (int i = tid; i < NB * HSTRIDE; i += THREADS) { Hhi[i] = 0u; Hlo[i] = 0u; }
    for (int i = tid; i < NB * 64; i += THREADS) {
        int b = i >> 6, s = i & 63;
        x_sh[0][b][s] = x[(size_t)(b0 + b) * T_LEN + s];
    }
    __syncthreads();

    for (int t = 0; t < T_LEN; ++t) {
        // ---- deferred output head for step t-1 (overlaps next MMA issue) ----
        if (t > 0) {
            float po = po_pend;
            #pragma unroll
            for (int off = 16; off > 0; off >>= 1)
                po += __shfl_xor_sync(0xffffffffu, po, off);
            if (lane == 0) out[(size_t)(b0 + wid) * T_LEN + (t - 1)] = po + bfc;
        }

        // ---- MMA phase: 3 independent accumulator chains (depth 4 each) ----
        float a0[2][4], a1[2][4], a2[2][4];
        #pragma unroll
        for (int mt = 0; mt < 2; ++mt)
            #pragma unroll
            for (int i = 0; i < 4; ++i) { a0[mt][i] = 0.f; a1[mt][i] = 0.f; a2[mt][i] = 0.f; }

        #pragma unroll
        for (int kt = 0; kt < 4; ++kt) {
            const int base = (8 * bh8 + qid) * HSTRIDE + 8 * kt + tig;
            uint32_t bhv0 = Hhi[base], bhv1 = Hhi[base + 4];
            uint32_t blv0 = Hlo[base], blv1 = Hlo[base + 4];
            #pragma unroll
            for (int mt = 0; mt < 2; ++mt) {
                MMA_BF16(a0[mt], whi[mt][kt], bhv0, bhv1);   // Whi*Hhi
                MMA_BF16(a1[mt], whi[mt][kt], blv0, blv1);   // Whi*Hlo
                MMA_BF16(a2[mt], wlo[mt][kt], bhv0, bhv1);   // Wlo*Hhi
            }
        }

        // ---- scatter gates to gbuf[b][g] (bank-verified conflict-free) ----
        #pragma unroll
        for (int mt = 0; mt < 2; ++mt) {
            const int g = 32 * wrow + 16 * mt + qid;
            const int b = 8 * bh8 + 2 * tig;
            gbuf[b * GP + g]           = a0[mt][0] + a1[mt][0] + a2[mt][0];
            gbuf[(b + 1) * GP + g]     = a0[mt][1] + a1[mt][1] + a2[mt][1];
            gbuf[b * GP + g + 8]       = a0[mt][2] + a1[mt][2] + a2[mt][2];
            gbuf[(b + 1) * GP + g + 8] = a0[mt][3] + a1[mt][3] + a2[mt][3];
        }
        HALF_BAR(bh8);                          // bar1: this half's gates visible

        // ---- update: warp = batch `wid`, units lane & lane+32 ----
        // gate = recurrent(MMA) + x*w_ih + (b_ih+b_hh), PyTorch order i,f,g,o
        const float xv = x_sh[(t >> 6) & 1][wid][t & 63];
        const float* gb = gbuf + wid * GP;
        float gi0 = gb[lane]       + fmaf(xv, wih_r[0], bias_r[0]);
        float gf0 = gb[lane + 64]  + fmaf(xv, wih_r[1], bias_r[1]);
        float gg0 = gb[lane + 128] + fmaf(xv, wih_r[2], bias_r[2]);
        float go0 = gb[lane + 192] + fmaf(xv, wih_r[3], bias_r[3]);
        float gi1 = gb[lane + 32]  + fmaf(xv, wih_r[4], bias_r[4]);
        float gf1 = gb[lane + 96]  + fmaf(xv, wih_r[5], bias_r[5]);
        float gg1 = gb[lane + 160] + fmaf(xv, wih_r[6], bias_r[6]);
        float go1 = gb[lane + 224] + fmaf(xv, wih_r[7], bias_r[7]);

        float iv0 = sigm(gi0), fv0 = sigm(gf0);
        float gv0 = tanh_mufu(gg0), ov0 = sigm(go0);
        c0 = fmaf(fv0, c0, iv0 * gv0);
        float hv0 = ov0 * tanh_mufu(c0);

        float iv1 = sigm(gi1), fv1 = sigm(gf1);
        float gv1 = tanh_mufu(gg1), ov1 = sigm(go1);
        c1 = fmaf(fv1, c1, iv1 * gv1);
        float hv1 = ov1 * tanh_mufu(c1);

        // H write (warp wid owns batch row wid)
        __nv_bfloat16 h0h = __float2bfloat16(hv0);
        __nv_bfloat16 h1h = __float2bfloat16(hv1);
        ((__nv_bfloat16*)Hhi)[wid * (2 * HSTRIDE) + lane]      = h0h;
        ((__nv_bfloat16*)Hhi)[wid * (2 * HSTRIDE) + lane + 32] = h1h;
        ((__nv_bfloat16*)Hlo)[wid * (2 * HSTRIDE) + lane] =
            __float2bfloat16(hv0 - __bfloat162float(h0h));
        ((__nv_bfloat16*)Hlo)[wid * (2 * HSTRIDE) + lane + 32] =
            __float2bfloat16(hv1 - __bfloat162float(h1h));

        // output partial, reduced after the barrier (next iteration)
        po_pend = fmaf(hv0, wfc0, hv1 * wfc1);

        // stage next 64-step x chunk at chunk start (half-local)
        if ((t & 63) == 0 && (t >> 6) + 1 < T_LEN / 64) {
            const int nc = (t >> 6) + 1;
            const int lt = tid & 255;
            #pragma unroll
            for (int q = 0; q < 2; ++q) {
                int idx = lt + 256 * q;                  // 0..511
                int b = 8 * bh8 + (idx >> 6);
                int s = idx & 63;
                x_sh[nc & 1][b][s] = x[(size_t)(b0 + b) * T_LEN + nc * 64 + s];
            }
        }
        HALF_BAR(bh8);                          // bar2: this half's H visible
    }

    // final deferred output (t = T_LEN-1)
    {
        float po = po_pend;
        #pragma unroll
        for (int off = 16; off > 0; off >>= 1)
            po += __shfl_xor_sync(0xffffffffu, po, off);
        if (lane == 0) out[(size_t)(b0 + wid) * T_LEN + (T_LEN - 1)] = po + bfc;
    }
}

extern "C" void kernel_launch(void* const* d_in, const int* in_sizes, int n_in,
                              void* d_out, int out_size)
{
    const float* x    = (const float*)d_in[0];
    const float* w_ih = (const float*)d_in[1];
    const float* w_hh = (const float*)d_in[2];
    const float* b_ih = (const float*)d_in[3];
    const float* b_hh = (const float*)d_in[4];
    const float* w_fc = (const float*)d_in[5];
    const float* b_fc = (const float*)d_in[6];
    float* out = (float*)d_out;

    lstm_kernel<<<BATCH / NB, THREADS>>>(x, w_ih, w_hh, b_ih, b_hh,
                                         w_fc, b_fc, out);
}